// round 14
// baseline (speedup 1.0000x reference)
#include <cuda_runtime.h>
#include <cstdint>
#include <cstddef>

// TensorFusion: B=32, N=4096, C=16, D=256
//   out[b,c,d]  = (1/N) * sum_n [r[b,n,c] >= 0.5] * v[b,n,d]        c in 0..15
//   out[b,16,d] = (1/N) * sum_n [all c: r[b,n,c] < 0.5] * v[b,n,d]

#define B_DIM 32
#define N_DIM 4096
#define C_DIM 16
#define D_DIM 256
#define OUT_C (C_DIM + 1)

#define SPLIT 16
#define NCHUNK (N_DIM / SPLIT)     // 256 rows per CTA
#define THREADS 256
#define RHALF (NCHUNK / 2)         // 128 rows per row-half
#define C_PAD 18                   // 17 mask pairs padded (16B-aligned rows)

#define RING_DEPTH 8               // rows in flight per warp
#define RING_ROW_BYTES 256         // 64 d x 4B per warp-row slice
#define MASKD_BYTES (NCHUNK * C_PAD * 8)                       // 36864
#define RING_BYTES  (8 * RING_DEPTH * RING_ROW_BYTES)          // 16384
#define SMEM_TOTAL  (MASKD_BYTES + RING_BYTES)                 // 53248

__global__ void tf_zero_kernel(float* __restrict__ out, int n) {
    int i = blockIdx.x * blockDim.x + threadIdx.x;
    if (i < n) out[i] = 0.0f;
}

// Packed f32x2 FMA: acc.{lo,hi} += m.{lo,hi} * v.{lo,hi}  (one FFMA2, fma pipe)
#define FMA2(acc, m, vv) \
    asm("fma.rn.f32x2 %0, %1, %2, %0;" : "+l"(acc) : "l"(m), "l"(vv))

__device__ __forceinline__ void cp_async8(uint32_t dst_smem, const void* src) {
    asm volatile("cp.async.ca.shared.global [%0], [%1], 8;"
                 :: "r"(dst_smem), "l"(src));
}
#define CP_COMMIT() asm volatile("cp.async.commit_group;" ::: "memory")
#define CP_WAIT7()  asm volatile("cp.async.wait_group 7;" ::: "memory")

extern __shared__ __align__(16) char dynsmem[];

__global__ __launch_bounds__(THREADS, 4)
void tf_fusion_kernel(const float* __restrict__ r,
                      const float* __restrict__ v,
                      float* __restrict__ out) {
    // Layout: [maskd: NCHUNK x C_PAD ull (reused as red[OUT_C][D_DIM] later)]
    //         [ring : 8 warps x RING_DEPTH x 256B]
    unsigned long long* maskd = reinterpret_cast<unsigned long long*>(dynsmem);
    char* ring = dynsmem + MASKD_BYTES;

    const int b    = blockIdx.y;
    const int n0   = blockIdx.x * NCHUNK;
    const int t    = threadIdx.x;
    const int w    = t >> 5;          // warp 0..7
    const int lane = t & 31;
    const int rh   = w >> 2;          // row half: rows [rh*128, rh*128+128)
    const int dcol = (w & 3) * 64 + lane * 2;   // owns d = dcol, dcol+1

    // ---- Phase A: 17 mask floats (0.0/1.0) per row, stored as dup pairs ----
    {
        const float4* rp = reinterpret_cast<const float4*>(
            r + (size_t)(b * N_DIM + n0 + t) * C_DIM);
        unsigned m = 0u;
        #pragma unroll
        for (int j = 0; j < 4; ++j) {
            float4 x = rp[j];
            m |= (x.x >= 0.5f ? 1u : 0u) << (4 * j + 0);
            m |= (x.y >= 0.5f ? 1u : 0u) << (4 * j + 1);
            m |= (x.z >= 0.5f ? 1u : 0u) << (4 * j + 2);
            m |= (x.w >= 0.5f ? 1u : 0u) << (4 * j + 3);
        }
        if (m == 0u) m = 1u << 16;   // special channel: no category matched
        #pragma unroll
        for (int c = 0; c < OUT_C; ++c) {
            unsigned u = ((m >> c) & 1u) ? 0x3f800000u : 0u;  // 1.0f or 0.0f
            maskd[(size_t)t * C_PAD + c] =
                (unsigned long long)u | ((unsigned long long)u << 32);
        }
    }
    __syncthreads();   // the ONLY barrier before the reduction

    // ---- Phase B: barrier-free per-warp cp.async pipeline ----
    unsigned long long acc[OUT_C];
    #pragma unroll
    for (int c = 0; c < OUT_C; ++c) acc[c] = 0ull;

    // Global source: this warp's d-slice of its row half (8B per lane per row).
    const float* gv = v + (size_t)(b * N_DIM + n0 + rh * RHALF) * D_DIM + dcol;

    // This warp's ring; lane's 8B slot within a ring row.
    uint32_t ring_u32;
    asm("{ .reg .u64 tt; cvta.to.shared.u64 tt, %1; cvt.u32.u64 %0, tt; }"
        : "=r"(ring_u32) : "l"(ring));
    const uint32_t rbase = ring_u32
                         + (uint32_t)(w * RING_DEPTH * RING_ROW_BYTES)
                         + (uint32_t)(lane * 8);
    const unsigned long long* rring = reinterpret_cast<unsigned long long*>(
        ring + w * RING_DEPTH * RING_ROW_BYTES + lane * 8);

    #define ISSUE_ROW(i)                                                       \
    do {                                                                       \
        cp_async8(rbase + (uint32_t)(((i) & (RING_DEPTH - 1)) * RING_ROW_BYTES),\
                  gv + (size_t)(i) * D_DIM);                                   \
        CP_COMMIT();                                                           \
    } while (0)

    // Prologue: rows 0..6 in flight (7 groups).
    #pragma unroll
    for (int i = 0; i < RING_DEPTH - 1; ++i) ISSUE_ROW(i);

    const unsigned long long* mbase = maskd + (size_t)(rh * RHALF) * C_PAD;

    #pragma unroll 2
    for (int i = 0; i < RHALF; ++i) {
        if (i + RING_DEPTH - 1 < RHALF) {
            ISSUE_ROW(i + RING_DEPTH - 1);
        } else {
            CP_COMMIT();              // empty group keeps the count advancing
        }
        CP_WAIT7();                   // own copy of row i complete (per-warp!)

        unsigned long long vpair =
            rring[(size_t)((i & (RING_DEPTH - 1)) * RING_ROW_BYTES) / 8];
        const unsigned long long* mrow = mbase + (size_t)i * C_PAD;
        #pragma unroll
        for (int c = 0; c < C_DIM; c += 2) {
            ulonglong2 mm = *reinterpret_cast<const ulonglong2*>(mrow + c);
            FMA2(acc[c],     mm.x, vpair);
            FMA2(acc[c + 1], mm.y, vpair);
        }
        FMA2(acc[16], mrow[16], vpair);
    }

    // ---- Phase C: cross-half reduce via smem (aliased over maskd) ----
    __syncthreads();                  // all mask reads done; maskd is dead
    float* red = reinterpret_cast<float*>(maskd);   // red[c*D_DIM + d]

    if (rh == 1) {
        #pragma unroll
        for (int c = 0; c < OUT_C; ++c) {
            *reinterpret_cast<float2*>(&red[c * D_DIM + dcol]) =
                *reinterpret_cast<const float2*>(&acc[c]);
        }
    }
    __syncthreads();

    if (rh == 0) {
        const float scale = 1.0f / (float)N_DIM;
        float* op = out + (size_t)b * OUT_C * D_DIM + dcol;
        #pragma unroll
        for (int c = 0; c < OUT_C; ++c) {
            float2 o = *reinterpret_cast<const float2*>(&red[c * D_DIM + dcol]);
            float2 a = *reinterpret_cast<const float2*>(&acc[c]);
            atomicAdd(op + c * D_DIM + 0, (a.x + o.x) * scale);
            atomicAdd(op + c * D_DIM + 1, (a.y + o.y) * scale);
        }
    }
}

extern "C" void kernel_launch(void* const* d_in, const int* in_sizes, int n_in,
                              void* d_out, int out_size) {
    // Inputs per metadata order: r_tensor (B*N*C), v_tensor (B*N*D).
    // Disambiguate defensively by element count.
    const float* r = (const float*)d_in[0];
    const float* v = (const float*)d_in[1];
    if (n_in >= 2 && in_sizes[0] == B_DIM * N_DIM * D_DIM &&
        in_sizes[1] == B_DIM * N_DIM * C_DIM) {
        r = (const float*)d_in[1];
        v = (const float*)d_in[0];
    }
    float* out = (float*)d_out;

    // Host-side attribute set (not a stream op; graph-capture safe, idempotent).
    cudaFuncSetAttribute(tf_fusion_kernel,
                         cudaFuncAttributeMaxDynamicSharedMemorySize, SMEM_TOTAL);

    const int out_elems = B_DIM * OUT_C * D_DIM;  // 139264
    tf_zero_kernel<<<(out_elems + 255) / 256, 256>>>(out, out_elems);

    dim3 grid(SPLIT, B_DIM);
    tf_fusion_kernel<<<grid, THREADS, SMEM_TOTAL>>>(r, v, out);
}

// round 15
// speedup vs baseline: 2.6187x; 2.6187x over previous
#include <cuda_runtime.h>
#include <cstdint>
#include <cstddef>

// TensorFusion: B=32, N=4096, C=16, D=256
//   out[b,c,d]  = (1/N) * sum_n [r[b,n,c] >= 0.5] * v[b,n,d]        c in 0..15
//   out[b,16,d] = (1/N) * sum_n [all c: r[b,n,c] < 0.5] * v[b,n,d]

#define B_DIM 32
#define N_DIM 4096
#define C_DIM 16
#define D_DIM 256
#define OUT_C (C_DIM + 1)

#define SPLIT 32
#define NCHUNK (N_DIM / SPLIT)     // 128 rows per CTA
#define THREADS 256
#define NHALF 64                   // rows per n-half
#define MF_PAD 20                  // 17 mask floats padded to 80B rows

#define S_STAGES 3                 // cp.async ring depth (stages in flight: 2)
#define RSTAGE 8                   // rows per stage per n-half
#define STAGE_ITERS (NHALF / RSTAGE)    // 8
#define ROW_BYTES (D_DIM * 4)      // 1 KB per v row
#define STAGE_BYTES (2 * RSTAGE * ROW_BYTES)   // 16 KB (both halves)

#define MASKF_BYTES (NCHUNK * MF_PAD * 4)      // 10240
#define POOL_BYTES  (S_STAGES * STAGE_BYTES)   // 49152 (>= red 17408)
#define SMEM_TOTAL  (MASKF_BYTES + POOL_BYTES) // 59392

__global__ void tf_zero_kernel(float* __restrict__ out, int n) {
    int i = blockIdx.x * blockDim.x + threadIdx.x;
    if (i < n) out[i] = 0.0f;
}

// Packed f32x2 FMA: acc.{lo,hi} += m.{lo,hi} * v.{lo,hi}  (one FFMA2, fma pipe)
#define FMA2(acc, m, vv) \
    asm("fma.rn.f32x2 %0, %1, %2, %0;" : "+l"(acc) : "l"(m), "l"(vv))
// Duplicate a float into both f32x2 lanes.
#define DUP2(dst, f) \
    asm("mov.b64 %0, {%1, %1};" : "=l"(dst) : "f"(f))

__device__ __forceinline__ void cp_async16(uint32_t dst_smem, const void* src) {
    asm volatile("cp.async.cg.shared.global [%0], [%1], 16;"
                 :: "r"(dst_smem), "l"(src));
}
#define CP_COMMIT() asm volatile("cp.async.commit_group;" ::: "memory")
#define CP_WAIT2()  asm volatile("cp.async.wait_group 2;" ::: "memory")

extern __shared__ __align__(16) char dynsmem[];

__global__ __launch_bounds__(THREADS, 3)
void tf_fusion_kernel(const float* __restrict__ r,
                      const float* __restrict__ v,
                      float* __restrict__ out) {
    // Layout: [maskf: NCHUNK x MF_PAD floats][pool: stage ring, reused as red]
    float* maskf = reinterpret_cast<float*>(dynsmem);
    char*  pool  = dynsmem + MASKF_BYTES;

    const int b  = blockIdx.y;
    const int n0 = blockIdx.x * NCHUNK;
    const int t  = threadIdx.x;
    const int q  = t & 63;         // d-quad index (owns d = 4q..4q+3)
    const int ch = (t >> 6) & 1;   // channel half: 0 -> pairs 0..3, 1 -> 4..7+sp
    const int h  = t >> 7;         // n-half (64 rows each)

    uint32_t pool_u32;
    asm("{ .reg .u64 tt; cvta.to.shared.u64 tt, %1; cvt.u32.u64 %0, tt; }"
        : "=r"(pool_u32) : "l"(pool));

    // ---- Phase A: 17 mask floats (0.0/1.0) per row (threads 0..127) ----
    if (t < NCHUNK) {
        const float4* rp = reinterpret_cast<const float4*>(
            r + (size_t)(b * N_DIM + n0 + t) * C_DIM);
        unsigned m = 0u;
        #pragma unroll
        for (int j = 0; j < 4; ++j) {
            float4 x = rp[j];
            m |= (x.x >= 0.5f ? 1u : 0u) << (4 * j + 0);
            m |= (x.y >= 0.5f ? 1u : 0u) << (4 * j + 1);
            m |= (x.z >= 0.5f ? 1u : 0u) << (4 * j + 2);
            m |= (x.w >= 0.5f ? 1u : 0u) << (4 * j + 3);
        }
        if (m == 0u) m = 1u << 16;   // special channel: no category matched
        #pragma unroll
        for (int c = 0; c < OUT_C; ++c) {
            maskf[t * MF_PAD + c] = (float)((m >> c) & 1u);
        }
    }

    // ---- cp.async sources: thread copies 4 x 16B per stage ----
    // Stage byte offset o = k*4096 + t*16 maps to (local row lr = o>>10, col).
    const float* gsrc[4];
    uint32_t     sdst[4];
    #pragma unroll
    for (int k = 0; k < 4; ++k) {
        int o   = k * 4096 + t * 16;
        int lr  = o >> 10;            // 0..15: half hs = lr>>3, row rr = lr&7
        int hs  = lr >> 3;
        int rr  = lr & 7;
        int col = o & 1023;
        gsrc[k] = v + (size_t)(b * N_DIM + n0 + hs * NHALF + rr) * D_DIM
                    + col / 4;
        sdst[k] = pool_u32 + (uint32_t)o;
    }
    #define ISSUE_STAGE(s)                                                     \
    do {                                                                       \
        uint32_t _soff = (uint32_t)(((s) % S_STAGES) * STAGE_BYTES);           \
        size_t   _goff = (size_t)((s) * RSTAGE) * D_DIM;                       \
        cp_async16(sdst[0] + _soff, gsrc[0] + _goff);                          \
        cp_async16(sdst[1] + _soff, gsrc[1] + _goff);                          \
        cp_async16(sdst[2] + _soff, gsrc[2] + _goff);                          \
        cp_async16(sdst[3] + _soff, gsrc[3] + _goff);                          \
        CP_COMMIT();                                                           \
    } while (0)

    // Prologue: stages 0 and 1 in flight.
    ISSUE_STAGE(0);
    ISSUE_STAGE(1);

    __syncthreads();   // maskf ready

    // ---- Phase B: staged streaming, FFMA2 packed over channel pairs ----
    // ch=0: pairs 0..3 (channels 0..7);  ch=1: pairs 4..7 + special ch16.
    unsigned long long accp[4][4];   // [pair][d]  lanes = (c_even, c_odd)
    unsigned long long accs[4];      // special channel (ch half 1 only)
    #pragma unroll
    for (int p = 0; p < 4; ++p)
        #pragma unroll
        for (int d = 0; d < 4; ++d) accp[p][d] = 0ull;
    #pragma unroll
    for (int d = 0; d < 4; ++d) accs[d] = 0ull;

    const float* mbase = maskf + (h * NHALF) * MF_PAD;
    const int pbase = ch * 4;        // first channel-pair index for this half

    #pragma unroll 1
    for (int i = 0; i < STAGE_ITERS; ++i) {
        if (i + 2 < STAGE_ITERS) ISSUE_STAGE(i + 2);
        else                     CP_COMMIT();   // keep group count advancing
        CP_WAIT2();                  // own copies of stage i complete
        __syncthreads();             // everyone's copies of stage i complete

        const char* vs = pool + ((i % S_STAGES) * STAGE_BYTES)
                              + (h * RSTAGE) * ROW_BYTES + q * 16;
        const float* mrow = mbase + (size_t)(i * RSTAGE) * MF_PAD;

        #pragma unroll
        for (int rr = 0; rr < RSTAGE; ++rr) {
            float4 x = *reinterpret_cast<const float4*>(vs + rr * ROW_BYTES);
            unsigned long long vd[4];
            DUP2(vd[0], x.x); DUP2(vd[1], x.y);
            DUP2(vd[2], x.z); DUP2(vd[3], x.w);
            const float* mr = mrow + rr * MF_PAD;
            #pragma unroll
            for (int p = 0; p < 4; ++p) {
                // broadcast LDS.64: mask pair (c=2*(pbase+p), c+1)
                unsigned long long mp = *reinterpret_cast<const unsigned long long*>(
                    mr + 2 * (pbase + p));
                FMA2(accp[p][0], mp, vd[0]);
                FMA2(accp[p][1], mp, vd[1]);
                FMA2(accp[p][2], mp, vd[2]);
                FMA2(accp[p][3], mp, vd[3]);
            }
            if (ch == 1) {
                unsigned long long ms;
                DUP2(ms, mr[16]);
                FMA2(accs[0], ms, vd[0]);
                FMA2(accs[1], ms, vd[1]);
                FMA2(accs[2], ms, vd[2]);
                FMA2(accs[3], ms, vd[3]);
            }
        }
        __syncthreads();             // all consumers done before slot reuse
    }

    // ---- Phase C: cross-half reduce via smem (aliased over pool) ----
    float* red = reinterpret_cast<float*>(pool);   // red[c*D_DIM + d]

    if (h == 1) {
        #pragma unroll
        for (int p = 0; p < 4; ++p) {
            int c0 = 2 * (pbase + p);
            #pragma unroll
            for (int d = 0; d < 4; ++d) {
                float2 f = *reinterpret_cast<const float2*>(&accp[p][d]);
                red[(c0 + 0) * D_DIM + q * 4 + d] = f.x;
                red[(c0 + 1) * D_DIM + q * 4 + d] = f.y;
            }
        }
        if (ch == 1) {
            #pragma unroll
            for (int d = 0; d < 4; ++d) {
                float2 f = *reinterpret_cast<const float2*>(&accs[d]);
                red[16 * D_DIM + q * 4 + d] = f.x;
            }
        }
    }
    __syncthreads();

    if (h == 0) {
        const float scale = 1.0f / (float)N_DIM;
        float* op = out + (size_t)b * OUT_C * D_DIM + q * 4;
        #pragma unroll
        for (int p = 0; p < 4; ++p) {
            int c0 = 2 * (pbase + p);
            #pragma unroll
            for (int d = 0; d < 4; ++d) {
                float2 f = *reinterpret_cast<const float2*>(&accp[p][d]);
                atomicAdd(op + (c0 + 0) * D_DIM + d,
                          (f.x + red[(c0 + 0) * D_DIM + q * 4 + d]) * scale);
                atomicAdd(op + (c0 + 1) * D_DIM + d,
                          (f.y + red[(c0 + 1) * D_DIM + q * 4 + d]) * scale);
            }
        }
        if (ch == 1) {
            #pragma unroll
            for (int d = 0; d < 4; ++d) {
                float2 f = *reinterpret_cast<const float2*>(&accs[d]);
                atomicAdd(op + 16 * D_DIM + d,
                          (f.x + red[16 * D_DIM + q * 4 + d]) * scale);
            }
        }
    }
}

extern "C" void kernel_launch(void* const* d_in, const int* in_sizes, int n_in,
                              void* d_out, int out_size) {
    // Inputs per metadata order: r_tensor (B*N*C), v_tensor (B*N*D).
    // Disambiguate defensively by element count.
    const float* r = (const float*)d_in[0];
    const float* v = (const float*)d_in[1];
    if (n_in >= 2 && in_sizes[0] == B_DIM * N_DIM * D_DIM &&
        in_sizes[1] == B_DIM * N_DIM * C_DIM) {
        r = (const float*)d_in[1];
        v = (const float*)d_in[0];
    }
    float* out = (float*)d_out;

    // Host-side attribute set (not a stream op; graph-capture safe, idempotent).
    cudaFuncSetAttribute(tf_fusion_kernel,
                         cudaFuncAttributeMaxDynamicSharedMemorySize, SMEM_TOTAL);

    const int out_elems = B_DIM * OUT_C * D_DIM;  // 139264
    tf_zero_kernel<<<(out_elems + 255) / 256, 256>>>(out, out_elems);

    dim3 grid(SPLIT, B_DIM);
    tf_fusion_kernel<<<grid, THREADS, SMEM_TOTAL>>>(r, v, out);
}